// round 1
// baseline (speedup 1.0000x reference)
#include <cuda_runtime.h>

// decoder_fm: out[b] = 0.5*(sum_k (x@V)_k^2 - sum_j x_j^2 * s_j) + x.w + fc_b
//                      + b_users[user[b]] + b_items[item[b]] + 4.0
// x = concat(user_emb[user[b]], item_emb[item[b]])  (128 floats)
// s_j = sum_k V[j][k]^2  (precomputed per block in smem)

__global__ __launch_bounds__(256) void fm_kernel(
    const int* __restrict__ user, const int* __restrict__ item,
    const float* __restrict__ user_emb, const float* __restrict__ item_emb,
    const float* __restrict__ fc_w, const float* __restrict__ fc_b,
    const float* __restrict__ fm_V,
    const float* __restrict__ b_users, const float* __restrict__ b_items,
    float* __restrict__ out, int nrows)
{
    __shared__ float  sw[128];        // fc_w
    __shared__ float  ss[128];        // sum_k V[j][k]^2
    __shared__ float2 sV[5][128];     // V pairs: sV[k2][j] = (V[j][2k2], V[j][2k2+1])

    int tid = threadIdx.x;
    if (tid < 128) {
        float v[10];
        #pragma unroll
        for (int k = 0; k < 10; k++) v[k] = fm_V[tid * 10 + k];
        float s = 0.f;
        #pragma unroll
        for (int k = 0; k < 10; k++) s = fmaf(v[k], v[k], s);
        ss[tid] = s;
        sw[tid] = fc_w[tid];
        #pragma unroll
        for (int k2 = 0; k2 < 5; k2++)
            sV[k2][tid] = make_float2(v[2 * k2], v[2 * k2 + 1]);
    }
    __syncthreads();

    const int lane = tid & 31;
    const int sub  = lane & 3;    // element-slice within a row
    const int rw   = lane >> 2;   // row within warp (0..7)
    const int warp = tid >> 5;    // 0..7
    const int row  = blockIdx.x * 64 + warp * 8 + rw;
    if (row >= nrows) return;

    const int u  = user[row];
    const int it = item[row];
    const float4* up = reinterpret_cast<const float4*>(user_emb + (long long)u  * 64);
    const float4* ip = reinterpret_cast<const float4*>(item_emb + (long long)it * 64);

    float lin = 0.f, x2s = 0.f;
    float xv[10];
    #pragma unroll
    for (int k = 0; k < 10; k++) xv[k] = 0.f;

    // Each lane handles chunks {sub, 4+sub, ..., 28+sub}: 32 of the 128 elements.
    #pragma unroll
    for (int i = 0; i < 8; i++) {
        const int chunk = i * 4 + sub;                 // 0..31, chunks 0..15 = user half
        float4 xq = (i < 4) ? up[chunk] : ip[chunk - 16];
        const int j0 = chunk * 4;

        const float4 wq = *reinterpret_cast<const float4*>(&sw[j0]);
        const float4 sq = *reinterpret_cast<const float4*>(&ss[j0]);
        const float xs[4] = {xq.x, xq.y, xq.z, xq.w};
        const float ws[4] = {wq.x, wq.y, wq.z, wq.w};
        const float s2[4] = {sq.x, sq.y, sq.z, sq.w};

        #pragma unroll
        for (int c = 0; c < 4; c++) {
            const float x = xs[c];
            lin = fmaf(x, ws[c], lin);
            x2s = fmaf(x * x, s2[c], x2s);
        }
        #pragma unroll
        for (int k2 = 0; k2 < 5; k2++) {
            const float4 va = *reinterpret_cast<const float4*>(&sV[k2][j0]);      // j0, j0+1
            const float4 vb = *reinterpret_cast<const float4*>(&sV[k2][j0 + 2]);  // j0+2, j0+3
            xv[2 * k2]     = fmaf(xs[0], va.x, xv[2 * k2]);
            xv[2 * k2 + 1] = fmaf(xs[0], va.y, xv[2 * k2 + 1]);
            xv[2 * k2]     = fmaf(xs[1], va.z, xv[2 * k2]);
            xv[2 * k2 + 1] = fmaf(xs[1], va.w, xv[2 * k2 + 1]);
            xv[2 * k2]     = fmaf(xs[2], vb.x, xv[2 * k2]);
            xv[2 * k2 + 1] = fmaf(xs[2], vb.y, xv[2 * k2 + 1]);
            xv[2 * k2]     = fmaf(xs[3], vb.z, xv[2 * k2]);
            xv[2 * k2 + 1] = fmaf(xs[3], vb.w, xv[2 * k2 + 1]);
        }
    }

    // Reduce the 12 partial sums across the 4 sub-lanes of this row.
    #pragma unroll
    for (int m = 1; m <= 2; m <<= 1) {
        lin += __shfl_xor_sync(0xFFFFFFFFu, lin, m);
        x2s += __shfl_xor_sync(0xFFFFFFFFu, x2s, m);
        #pragma unroll
        for (int k = 0; k < 10; k++)
            xv[k] += __shfl_xor_sync(0xFFFFFFFFu, xv[k], m);
    }

    if (sub == 0) {
        float inter = -x2s;
        #pragma unroll
        for (int k = 0; k < 10; k++) inter = fmaf(xv[k], xv[k], inter);
        const float r = 0.5f * inter + lin + fc_b[0]
                      + b_users[u] + b_items[it] + 4.0f;
        out[row] = r;
    }
}

extern "C" void kernel_launch(void* const* d_in, const int* in_sizes, int n_in,
                              void* d_out, int out_size)
{
    // metadata order: user, item, u_out, i_out, user_emb, item_emb,
    //                 fc_w, fc_b, fm_V, b_users, b_items
    const int*   user     = (const int*)d_in[0];
    const int*   item     = (const int*)d_in[1];
    const float* user_emb = (const float*)d_in[4];
    const float* item_emb = (const float*)d_in[5];
    const float* fc_w     = (const float*)d_in[6];
    const float* fc_b     = (const float*)d_in[7];
    const float* fm_V     = (const float*)d_in[8];
    const float* b_users  = (const float*)d_in[9];
    const float* b_items  = (const float*)d_in[10];
    float* out = (float*)d_out;

    const int nrows = in_sizes[0];
    const int grid  = (nrows + 63) / 64;   // 64 rows per 256-thread block
    fm_kernel<<<grid, 256>>>(user, item, user_emb, item_emb,
                             fc_w, fc_b, fm_V, b_users, b_items, out, nrows);
}